// round 2
// baseline (speedup 1.0000x reference)
#include <cuda_runtime.h>
#include <math.h>

// ---------------- problem constants ----------------
#define B_    32
#define H_    56
#define W_    56
#define C_    512
#define HEADS 16
#define WSZ   7
#define SSZ   3
#define NTOK  49          // WSZ*WSZ
#define NWIN  64          // (H/WS)*(W/WS)
#define HD    32          // C/HEADS
#define HID_  2048
#define MTOK  100352      // B*H*W = B*NW*N
#define SCALE 0.17677669529663689f  // HD^-0.5

// ---------------- static scratch arena (kept < 2GB to avoid GOTPCREL
// relocation overflow in the host link) ----------------
// slot0: x1   [MTOK*C]            offset 0
// slot1: hwin / attn / ln2 [MTOK*C]   offset SLOT1
// slot2: qkv [MTOK*1536] / hid [MTOK*2048]  offset SLOT2
#define SLOT_TOK_C   ((size_t)MTOK * C_)          // 51,380,224 floats
#define SLOT1_OFF    SLOT_TOK_C
#define SLOT2_OFF    (2 * SLOT_TOK_C)
#define ARENA_FLOATS (2 * SLOT_TOK_C + (size_t)MTOK * HID_)   // ~1.15 GiB
__device__ float g_arena[ARENA_FLOATS];

// map window-layout row r -> pixel-layout row p (handles cyclic shift both ways)
__device__ __forceinline__ int win_row_to_pixel(int r) {
    int b   = r / (NWIN * NTOK);
    int rem = r - b * (NWIN * NTOK);
    int wi  = rem / NTOK;
    int n   = rem - wi * NTOK;
    int wh = wi >> 3, ww = wi & 7;
    int ih = n / WSZ, iw = n - ih * WSZ;
    int sr = wh * WSZ + ih;          // rolled-image coords
    int sc = ww * WSZ + iw;
    int orow = sr + SSZ; if (orow >= H_) orow -= H_;
    int ocol = sc + SSZ; if (ocol >= W_) ocol -= W_;
    return b * (H_ * W_) + orow * W_ + ocol;
}

// ---------------- LayerNorm (optionally fused with shift+window gather) ----
// one block per token, 128 threads, float4 per thread (C=512)
__global__ __launch_bounds__(128) void ln_kernel(
    const float* __restrict__ x, const float* __restrict__ g,
    const float* __restrict__ b, float* __restrict__ out, int windowMap)
{
    int r = blockIdx.x;
    int p = windowMap ? win_row_to_pixel(r) : r;
    int t = threadIdx.x;

    float4 v = ((const float4*)(x + (size_t)p * C_))[t];
    float s  = v.x + v.y + v.z + v.w;
    float sq = v.x*v.x + v.y*v.y + v.z*v.z + v.w*v.w;
    #pragma unroll
    for (int o = 16; o; o >>= 1) {
        s  += __shfl_xor_sync(0xffffffffu, s,  o);
        sq += __shfl_xor_sync(0xffffffffu, sq, o);
    }
    __shared__ float ss[4], ssq[4];
    __shared__ float sh_mean, sh_rstd;
    int w = t >> 5;
    if ((t & 31) == 0) { ss[w] = s; ssq[w] = sq; }
    __syncthreads();
    if (t == 0) {
        float S = ss[0] + ss[1] + ss[2] + ss[3];
        float Q = ssq[0] + ssq[1] + ssq[2] + ssq[3];
        float m = S * (1.0f / C_);
        float var = Q * (1.0f / C_) - m * m;
        sh_mean = m;
        sh_rstd = rsqrtf(var + 1e-5f);
    }
    __syncthreads();
    float m = sh_mean, rs = sh_rstd;
    float4 gg = ((const float4*)g)[t];
    float4 bb = ((const float4*)b)[t];
    float4 o;
    o.x = (v.x - m) * rs * gg.x + bb.x;
    o.y = (v.y - m) * rs * gg.y + bb.y;
    o.z = (v.z - m) * rs * gg.z + bb.z;
    o.w = (v.w - m) * rs * gg.w + bb.w;
    ((float4*)(out + (size_t)r * C_))[t] = o;
}

// ---------------- fp32 tiled GEMM: C[M,N] = A[M,K] * W[N,K]^T + bias --------
// EPI: 0 = bias only; 1 = bias + exact GELU; 2 = bias + window->pixel permute
//      + residual add (skip in pixel layout); 3 = bias + residual (identity map)
template<int EPI>
__global__ __launch_bounds__(256, 2) void gemm_kernel(
    const float* __restrict__ A, const float* __restrict__ Wt,
    const float* __restrict__ bias, float* __restrict__ C,
    int M, int N, int K, const float* __restrict__ skip)
{
    __shared__ float As[8][128];
    __shared__ float Bs[8][128];

    int tid = threadIdx.x;
    int tx = tid & 15, ty = tid >> 4;
    int rowBase = blockIdx.y * 128;
    int colBase = blockIdx.x * 128;

    int lr = tid >> 1;          // 0..127
    int lc = (tid & 1) * 4;     // 0 or 4

    const float* Ap = A  + (size_t)(rowBase + lr) * K + lc;
    const float* Wp = Wt + (size_t)(colBase + lr) * K + lc;

    float acc[8][8];
    #pragma unroll
    for (int i = 0; i < 8; i++)
        #pragma unroll
        for (int j = 0; j < 8; j++) acc[i][j] = 0.f;

    for (int k0 = 0; k0 < K; k0 += 8) {
        float4 a  = *(const float4*)(Ap + k0);
        float4 bv = *(const float4*)(Wp + k0);
        As[lc + 0][lr] = a.x;  As[lc + 1][lr] = a.y;
        As[lc + 2][lr] = a.z;  As[lc + 3][lr] = a.w;
        Bs[lc + 0][lr] = bv.x; Bs[lc + 1][lr] = bv.y;
        Bs[lc + 2][lr] = bv.z; Bs[lc + 3][lr] = bv.w;
        __syncthreads();
        #pragma unroll
        for (int k = 0; k < 8; k++) {
            float ar[8], br[8];
            #pragma unroll
            for (int i = 0; i < 8; i++) ar[i] = As[k][ty + 16 * i];
            #pragma unroll
            for (int j = 0; j < 8; j++) br[j] = Bs[k][tx + 16 * j];
            #pragma unroll
            for (int i = 0; i < 8; i++)
                #pragma unroll
                for (int j = 0; j < 8; j++)
                    acc[i][j] = fmaf(ar[i], br[j], acc[i][j]);
        }
        __syncthreads();
    }

    #pragma unroll
    for (int i = 0; i < 8; i++) {
        int row = rowBase + ty + 16 * i;
        size_t orow = row;
        if (EPI == 2) orow = win_row_to_pixel(row);
        #pragma unroll
        for (int j = 0; j < 8; j++) {
            int col = colBase + tx + 16 * j;
            float v = acc[i][j] + bias[col];
            if (EPI == 1) v = 0.5f * v * (1.0f + erff(v * 0.70710678118654752f));
            if (EPI == 2 || EPI == 3) v += skip[orow * (size_t)N + col];
            C[orow * (size_t)N + col] = v;
        }
    }
}

// ---------------- windowed attention: one block per (window, head) ----------
__device__ __forceinline__ int swin_region(int r) {
    // slices: [0,49) -> 0, [49,53) -> 1, [53,56) -> 2
    return (r < H_ - WSZ) ? 0 : ((r < H_ - SSZ) ? 1 : 2);
}

__global__ __launch_bounds__(256) void attn_kernel(const float* __restrict__ rel_bias)
{
    int w = blockIdx.x >> 4;     // window 0..2047
    int h = blockIdx.x & 15;     // head

    __shared__ float qs[NTOK][HD];
    __shared__ float ks[NTOK][HD];
    __shared__ float vs[NTOK][HD];
    __shared__ float s[NTOK][NTOK + 1];

    int tid = threadIdx.x;
    const float* base = g_arena + SLOT2_OFF + (size_t)w * NTOK * (3 * C_);

    for (int e = tid; e < NTOK * HD; e += 256) {
        int n = e >> 5, d = e & 31;
        size_t off = (size_t)n * (3 * C_) + h * HD + d;
        qs[n][d] = base[off] * SCALE;
        ks[n][d] = base[off + C_];
        vs[n][d] = base[off + 2 * C_];
    }
    __syncthreads();

    int wi = w & 63;
    int wh = wi >> 3, ww = wi & 7;

    for (int e = tid; e < NTOK * NTOK; e += 256) {
        int n = e / NTOK;
        int m = e - NTOK * n;
        float dot = 0.f;
        #pragma unroll
        for (int d = 0; d < HD; d++) dot += qs[n][d] * ks[m][d];
        int i1 = n / WSZ, j1 = n - i1 * WSZ;
        int i2 = m / WSZ, j2 = m - i2 * WSZ;
        int idx = (i1 - i2 + WSZ - 1) * (2 * WSZ - 1) + (j1 - j2 + WSZ - 1);
        dot += rel_bias[idx * HEADS + h];
        int l1 = swin_region(wh * WSZ + i1) * 3 + swin_region(ww * WSZ + j1);
        int l2 = swin_region(wh * WSZ + i2) * 3 + swin_region(ww * WSZ + j2);
        if (l1 != l2) dot -= 100.f;
        s[n][m] = dot;
    }
    __syncthreads();

    if (tid < NTOK) {
        float mx = -1e30f;
        #pragma unroll 7
        for (int m = 0; m < NTOK; m++) mx = fmaxf(mx, s[tid][m]);
        float sum = 0.f;
        #pragma unroll 7
        for (int m = 0; m < NTOK; m++) {
            float e = __expf(s[tid][m] - mx);
            s[tid][m] = e;
            sum += e;
        }
        float inv = 1.0f / sum;
        #pragma unroll 7
        for (int m = 0; m < NTOK; m++) s[tid][m] *= inv;
    }
    __syncthreads();

    // attn output goes into slot1 (reusing hwin's space)
    float* outb = g_arena + SLOT1_OFF + (size_t)w * NTOK * C_ + h * HD;
    for (int e = tid; e < NTOK * HD; e += 256) {
        int n = e >> 5, d = e & 31;
        float acc = 0.f;
        #pragma unroll 7
        for (int m = 0; m < NTOK; m++) acc += s[n][m] * vs[m][d];
        outb[(size_t)n * C_ + d] = acc;
    }
}

// ---------------- host launcher ----------------
extern "C" void kernel_launch(void* const* d_in, const int* in_sizes, int n_in,
                              void* d_out, int out_size)
{
    const float* x       = (const float*)d_in[0];
    const float* n1g     = (const float*)d_in[1];
    const float* n1b     = (const float*)d_in[2];
    const float* qkv_w   = (const float*)d_in[3];
    const float* qkv_b   = (const float*)d_in[4];
    const float* relb    = (const float*)d_in[5];
    const float* proj_w  = (const float*)d_in[6];
    const float* proj_b  = (const float*)d_in[7];
    const float* n2g     = (const float*)d_in[8];
    const float* n2b     = (const float*)d_in[9];
    const float* mlp_w1  = (const float*)d_in[10];
    const float* mlp_b1  = (const float*)d_in[11];
    const float* mlp_w2  = (const float*)d_in[12];
    const float* mlp_b2  = (const float*)d_in[13];
    float* out = (float*)d_out;

    float* arena;
    cudaGetSymbolAddress((void**)&arena, g_arena);

    float* x1   = arena;               // slot0
    float* s1   = arena + SLOT1_OFF;   // slot1: hwin -> attn -> ln2
    float* s2   = arena + SLOT2_OFF;   // slot2: qkv -> hid

    // 1) LN1 + shift + window partition  (hwin = s1)
    ln_kernel<<<MTOK, 128>>>(x, n1g, n1b, s1, 1);

    // 2) QKV projection: [100352,512] x [1536,512]^T  (qkv = s2)
    gemm_kernel<0><<<dim3(1536 / 128, MTOK / 128), 256>>>(
        s1, qkv_w, qkv_b, s2, MTOK, 3 * C_, C_, nullptr);

    // 3) windowed attention (reads s2, writes attn = s1)
    attn_kernel<<<2048 * HEADS, 256>>>(relb);

    // 4) proj + reverse-window/shift + residual -> x1 (pixel layout)
    gemm_kernel<2><<<dim3(C_ / 128, MTOK / 128), 256>>>(
        s1, proj_w, proj_b, x1, MTOK, C_, C_, x);

    // 5) LN2 (ln2 = s1)
    ln_kernel<<<MTOK, 128>>>(x1, n2g, n2b, s1, 0);

    // 6) MLP up + GELU  (hid = s2)
    gemm_kernel<1><<<dim3(HID_ / 128, MTOK / 128), 256>>>(
        s1, mlp_w1, mlp_b1, s2, MTOK, HID_, C_, nullptr);

    // 7) MLP down + residual -> out
    gemm_kernel<3><<<dim3(C_ / 128, MTOK / 128), 256>>>(
        s2, mlp_w2, mlp_b2, out, MTOK, C_, HID_, x1);
}

// round 3
// speedup vs baseline: 2.5446x; 2.5446x over previous
#include <cuda_runtime.h>
#include <math.h>
#include <stdint.h>

// ---------------- problem constants ----------------
#define B_    32
#define H_    56
#define W_    56
#define C_    512
#define HEADS 16
#define WSZ   7
#define SSZ   3
#define NTOK  49          // WSZ*WSZ
#define NWIN  64          // (H/WS)*(W/WS)
#define HD    32          // C/HEADS
#define HID_  2048
#define MTOK  100352      // B*H*W = B*NW*N
#define SCALE 0.17677669529663689f  // HD^-0.5

// ---------------- static scratch arena (< 2GB to keep host link happy) ----
// slot0: x1   [MTOK*C]
// slot1: hwin / attn / ln2 [MTOK*C]
// slot2: qkv [MTOK*1536] / hid [MTOK*2048]
#define SLOT_TOK_C   ((size_t)MTOK * C_)
#define SLOT1_OFF    SLOT_TOK_C
#define SLOT2_OFF    (2 * SLOT_TOK_C)
#define ARENA_FLOATS (2 * SLOT_TOK_C + (size_t)MTOK * HID_)   // ~1.15 GiB
__device__ float g_arena[ARENA_FLOATS];

// map window-layout row r -> pixel-layout row p (handles cyclic shift both ways)
__device__ __forceinline__ int win_row_to_pixel(int r) {
    int b   = r / (NWIN * NTOK);
    int rem = r - b * (NWIN * NTOK);
    int wi  = rem / NTOK;
    int n   = rem - wi * NTOK;
    int wh = wi >> 3, ww = wi & 7;
    int ih = n / WSZ, iw = n - ih * WSZ;
    int sr = wh * WSZ + ih;
    int sc = ww * WSZ + iw;
    int orow = sr + SSZ; if (orow >= H_) orow -= H_;
    int ocol = sc + SSZ; if (ocol >= W_) ocol -= W_;
    return b * (H_ * W_) + orow * W_ + ocol;
}

// ---------------- LayerNorm (optionally fused with shift+window gather) ----
__global__ __launch_bounds__(128) void ln_kernel(
    const float* __restrict__ x, const float* __restrict__ g,
    const float* __restrict__ b, float* __restrict__ out, int windowMap)
{
    int r = blockIdx.x;
    int p = windowMap ? win_row_to_pixel(r) : r;
    int t = threadIdx.x;

    float4 v = ((const float4*)(x + (size_t)p * C_))[t];
    float s  = v.x + v.y + v.z + v.w;
    float sq = v.x*v.x + v.y*v.y + v.z*v.z + v.w*v.w;
    #pragma unroll
    for (int o = 16; o; o >>= 1) {
        s  += __shfl_xor_sync(0xffffffffu, s,  o);
        sq += __shfl_xor_sync(0xffffffffu, sq, o);
    }
    __shared__ float ss[4], ssq[4];
    __shared__ float sh_mean, sh_rstd;
    int w = t >> 5;
    if ((t & 31) == 0) { ss[w] = s; ssq[w] = sq; }
    __syncthreads();
    if (t == 0) {
        float S = ss[0] + ss[1] + ss[2] + ss[3];
        float Q = ssq[0] + ssq[1] + ssq[2] + ssq[3];
        float m = S * (1.0f / C_);
        float var = Q * (1.0f / C_) - m * m;
        sh_mean = m;
        sh_rstd = rsqrtf(var + 1e-5f);
    }
    __syncthreads();
    float m = sh_mean, rs = sh_rstd;
    float4 gg = ((const float4*)g)[t];
    float4 bb = ((const float4*)b)[t];
    float4 o;
    o.x = (v.x - m) * rs * gg.x + bb.x;
    o.y = (v.y - m) * rs * gg.y + bb.y;
    o.z = (v.z - m) * rs * gg.z + bb.z;
    o.w = (v.w - m) * rs * gg.w + bb.w;
    ((float4*)(out + (size_t)r * C_))[t] = o;
}

// ---------------- tf32 tensor-core GEMM --------------------------------
// C[M,N] = A[M,K] @ Wt[N,K]^T + bias, with epilogues:
// EPI: 0 = bias; 1 = bias + exact GELU; 2 = bias + window->pixel permute +
//      residual; 3 = bias + residual
__device__ __forceinline__ uint32_t f2tf32(float f) {
    uint32_t u;
    asm("cvt.rna.tf32.f32 %0, %1;" : "=r"(u) : "f"(f));
    return u;
}

__device__ __forceinline__ void mma_tf32(float* c, const uint32_t* a, const uint32_t* b) {
    asm volatile(
        "mma.sync.aligned.m16n8k8.row.col.f32.tf32.tf32.f32 "
        "{%0,%1,%2,%3},{%4,%5,%6,%7},{%8,%9},{%0,%1,%2,%3};"
        : "+f"(c[0]), "+f"(c[1]), "+f"(c[2]), "+f"(c[3])
        : "r"(a[0]), "r"(a[1]), "r"(a[2]), "r"(a[3]), "r"(b[0]), "r"(b[1]));
}

template<int EPI>
__global__ __launch_bounds__(256) void gemm_tc(
    const float* __restrict__ A, const float* __restrict__ Wt,
    const float* __restrict__ bias, float* __restrict__ C,
    int M, int N, int K, const float* __restrict__ skip)
{
    // pad 36: fragment lds bank = (4*(lane/4) + lane%4) % 32 -> conflict-free
    __shared__ uint32_t As[128][36];
    __shared__ uint32_t Bs[128][36];

    int tid  = threadIdx.x;
    int lane = tid & 31;
    int wid  = tid >> 5;
    int warpM = wid & 3;      // 4 warps over M (4*32 = 128)
    int warpN = wid >> 2;     // 2 warps over N (2*64 = 128)
    int rowBase = blockIdx.y * 128;
    int colBase = blockIdx.x * 128;

    // global load mapping: tid%8 -> k chunk (4 floats), tid/8 -> row (+32*i)
    int gk = (tid & 7) * 4;
    int gr = tid >> 3;

    const float* Ap = A  + (size_t)(rowBase + gr) * K + gk;
    const float* Bp = Wt + (size_t)(colBase + gr) * K + gk;

    float acc[2][8][4];
    #pragma unroll
    for (int mi = 0; mi < 2; mi++)
        #pragma unroll
        for (int ni = 0; ni < 8; ni++)
            #pragma unroll
            for (int q = 0; q < 4; q++) acc[mi][ni][q] = 0.f;

    float4 ra[4], rb[4];
    #pragma unroll
    for (int i = 0; i < 4; i++) {
        ra[i] = *(const float4*)(Ap + (size_t)(32 * i) * K);
        rb[i] = *(const float4*)(Bp + (size_t)(32 * i) * K);
    }

    for (int kt = 0; kt < K; kt += 32) {
        #pragma unroll
        for (int i = 0; i < 4; i++) {
            uint4 av, bv;
            av.x = f2tf32(ra[i].x); av.y = f2tf32(ra[i].y);
            av.z = f2tf32(ra[i].z); av.w = f2tf32(ra[i].w);
            bv.x = f2tf32(rb[i].x); bv.y = f2tf32(rb[i].y);
            bv.z = f2tf32(rb[i].z); bv.w = f2tf32(rb[i].w);
            *(uint4*)&As[gr + 32 * i][gk] = av;
            *(uint4*)&Bs[gr + 32 * i][gk] = bv;
        }
        __syncthreads();

        if (kt + 32 < K) {
            #pragma unroll
            for (int i = 0; i < 4; i++) {
                ra[i] = *(const float4*)(Ap + (size_t)(32 * i) * K + kt + 32);
                rb[i] = *(const float4*)(Bp + (size_t)(32 * i) * K + kt + 32);
            }
        }

        #pragma unroll
        for (int ks = 0; ks < 4; ks++) {
            int k0 = ks * 8;
            uint32_t af[2][4], bf[8][2];
            #pragma unroll
            for (int mi = 0; mi < 2; mi++) {
                int r = warpM * 32 + mi * 16 + (lane >> 2);
                af[mi][0] = As[r    ][k0 + (lane & 3)];
                af[mi][1] = As[r + 8][k0 + (lane & 3)];
                af[mi][2] = As[r    ][k0 + (lane & 3) + 4];
                af[mi][3] = As[r + 8][k0 + (lane & 3) + 4];
            }
            #pragma unroll
            for (int ni = 0; ni < 8; ni++) {
                int c = warpN * 64 + ni * 8 + (lane >> 2);
                bf[ni][0] = Bs[c][k0 + (lane & 3)];
                bf[ni][1] = Bs[c][k0 + (lane & 3) + 4];
            }
            #pragma unroll
            for (int mi = 0; mi < 2; mi++)
                #pragma unroll
                for (int ni = 0; ni < 8; ni++)
                    mma_tf32(acc[mi][ni], af[mi], bf[ni]);
        }
        __syncthreads();
    }

    // ---------------- epilogue ----------------
    #pragma unroll
    for (int mi = 0; mi < 2; mi++) {
        int r0 = rowBase + warpM * 32 + mi * 16 + (lane >> 2);
        size_t o0 = (EPI == 2) ? (size_t)win_row_to_pixel(r0)     : (size_t)r0;
        size_t o1 = (EPI == 2) ? (size_t)win_row_to_pixel(r0 + 8) : (size_t)(r0 + 8);
        #pragma unroll
        for (int ni = 0; ni < 8; ni++) {
            int c0 = colBase + warpN * 64 + ni * 8 + (lane & 3) * 2;
            float b0 = bias[c0], b1 = bias[c0 + 1];

            float v0 = acc[mi][ni][0] + b0;
            float v1 = acc[mi][ni][1] + b1;
            float v2 = acc[mi][ni][2] + b0;
            float v3 = acc[mi][ni][3] + b1;
            if (EPI == 1) {
                v0 = 0.5f * v0 * (1.0f + erff(v0 * 0.70710678118654752f));
                v1 = 0.5f * v1 * (1.0f + erff(v1 * 0.70710678118654752f));
                v2 = 0.5f * v2 * (1.0f + erff(v2 * 0.70710678118654752f));
                v3 = 0.5f * v3 * (1.0f + erff(v3 * 0.70710678118654752f));
            }
            if (EPI == 2 || EPI == 3) {
                v0 += skip[o0 * (size_t)N + c0];
                v1 += skip[o0 * (size_t)N + c0 + 1];
                v2 += skip[o1 * (size_t)N + c0];
                v3 += skip[o1 * (size_t)N + c0 + 1];
            }
            *(float2*)&C[o0 * (size_t)N + c0] = make_float2(v0, v1);
            *(float2*)&C[o1 * (size_t)N + c0] = make_float2(v2, v3);
        }
    }
}

// ---------------- windowed attention: one block per (window, head) ----------
__device__ __forceinline__ int swin_region(int r) {
    return (r < H_ - WSZ) ? 0 : ((r < H_ - SSZ) ? 1 : 2);
}

__global__ __launch_bounds__(256) void attn_kernel(const float* __restrict__ rel_bias)
{
    int w = blockIdx.x >> 4;
    int h = blockIdx.x & 15;

    __shared__ float qs[NTOK][HD];
    __shared__ float ks[NTOK][HD];
    __shared__ float vs[NTOK][HD];
    __shared__ float s[NTOK][NTOK + 1];

    int tid = threadIdx.x;
    const float* base = g_arena + SLOT2_OFF + (size_t)w * NTOK * (3 * C_);

    for (int e = tid; e < NTOK * HD; e += 256) {
        int n = e >> 5, d = e & 31;
        size_t off = (size_t)n * (3 * C_) + h * HD + d;
        qs[n][d] = base[off] * SCALE;
        ks[n][d] = base[off + C_];
        vs[n][d] = base[off + 2 * C_];
    }
    __syncthreads();

    int wi = w & 63;
    int wh = wi >> 3, ww = wi & 7;

    for (int e = tid; e < NTOK * NTOK; e += 256) {
        int n = e / NTOK;
        int m = e - NTOK * n;
        float dot = 0.f;
        #pragma unroll
        for (int d = 0; d < HD; d++) dot += qs[n][d] * ks[m][d];
        int i1 = n / WSZ, j1 = n - i1 * WSZ;
        int i2 = m / WSZ, j2 = m - i2 * WSZ;
        int idx = (i1 - i2 + WSZ - 1) * (2 * WSZ - 1) + (j1 - j2 + WSZ - 1);
        dot += rel_bias[idx * HEADS + h];
        int l1 = swin_region(wh * WSZ + i1) * 3 + swin_region(ww * WSZ + j1);
        int l2 = swin_region(wh * WSZ + i2) * 3 + swin_region(ww * WSZ + j2);
        if (l1 != l2) dot -= 100.f;
        s[n][m] = dot;
    }
    __syncthreads();

    if (tid < NTOK) {
        float mx = -1e30f;
        #pragma unroll 7
        for (int m = 0; m < NTOK; m++) mx = fmaxf(mx, s[tid][m]);
        float sum = 0.f;
        #pragma unroll 7
        for (int m = 0; m < NTOK; m++) {
            float e = __expf(s[tid][m] - mx);
            s[tid][m] = e;
            sum += e;
        }
        float inv = 1.0f / sum;
        #pragma unroll 7
        for (int m = 0; m < NTOK; m++) s[tid][m] *= inv;
    }
    __syncthreads();

    float* outb = g_arena + SLOT1_OFF + (size_t)w * NTOK * C_ + h * HD;
    for (int e = tid; e < NTOK * HD; e += 256) {
        int n = e >> 5, d = e & 31;
        float acc = 0.f;
        #pragma unroll 7
        for (int m = 0; m < NTOK; m++) acc += s[n][m] * vs[m][d];
        outb[(size_t)n * C_ + d] = acc;
    }
}

// ---------------- host launcher ----------------
extern "C" void kernel_launch(void* const* d_in, const int* in_sizes, int n_in,
                              void* d_out, int out_size)
{
    const float* x       = (const float*)d_in[0];
    const float* n1g     = (const float*)d_in[1];
    const float* n1b     = (const float*)d_in[2];
    const float* qkv_w   = (const float*)d_in[3];
    const float* qkv_b   = (const float*)d_in[4];
    const float* relb    = (const float*)d_in[5];
    const float* proj_w  = (const float*)d_in[6];
    const float* proj_b  = (const float*)d_in[7];
    const float* n2g     = (const float*)d_in[8];
    const float* n2b     = (const float*)d_in[9];
    const float* mlp_w1  = (const float*)d_in[10];
    const float* mlp_b1  = (const float*)d_in[11];
    const float* mlp_w2  = (const float*)d_in[12];
    const float* mlp_b2  = (const float*)d_in[13];
    float* out = (float*)d_out;

    float* arena;
    cudaGetSymbolAddress((void**)&arena, g_arena);

    float* x1 = arena;               // slot0
    float* s1 = arena + SLOT1_OFF;   // slot1: hwin -> attn -> ln2
    float* s2 = arena + SLOT2_OFF;   // slot2: qkv -> hid

    // 1) LN1 + shift + window partition
    ln_kernel<<<MTOK, 128>>>(x, n1g, n1b, s1, 1);

    // 2) QKV projection
    gemm_tc<0><<<dim3(1536 / 128, MTOK / 128), 256>>>(
        s1, qkv_w, qkv_b, s2, MTOK, 3 * C_, C_, nullptr);

    // 3) windowed attention
    attn_kernel<<<2048 * HEADS, 256>>>(relb);

    // 4) proj + reverse-window/shift + residual -> x1
    gemm_tc<2><<<dim3(C_ / 128, MTOK / 128), 256>>>(
        s1, proj_w, proj_b, x1, MTOK, C_, C_, x);

    // 5) LN2
    ln_kernel<<<MTOK, 128>>>(x1, n2g, n2b, s1, 0);

    // 6) MLP up + GELU
    gemm_tc<1><<<dim3(HID_ / 128, MTOK / 128), 256>>>(
        s1, mlp_w1, mlp_b1, s2, MTOK, HID_, C_, nullptr);

    // 7) MLP down + residual -> out
    gemm_tc<3><<<dim3(C_ / 128, MTOK / 128), 256>>>(
        s2, mlp_w2, mlp_b2, out, MTOK, C_, HID_, x1);
}